// round 14
// baseline (speedup 1.0000x reference)
#include <cuda_runtime.h>
#include <cuda_bf16.h>
#include <cstdint>

#define FF  512
#define HD  64
#define NH  8
#define NC  10
#define NMAX 50000
#define EMAX 1700000
#define SCANB 256
#define NBMAX ((NMAX + SCANB - 1) / SCANB)

// -------- scratch (static device globals; no allocation allowed) ----------
static __device__ float g_h1  [NMAX*HD];
static __device__ float g_as1 [NMAX*NH];
static __device__ float g_ad1 [NMAX*NH];
static __device__ float g_h2p [NMAX*12];   // h2[0..9], slot10 = a_src2·h2
static __device__ float g_ad2 [NMAX];
static __device__ int   g_cnt [NMAX];
static __device__ int   g_off [NMAX+1];
static __device__ int   g_cur [NMAX];
static __device__ int   g_csr [EMAX];
static __device__ int   g_bsum[NBMAX];
static __device__ int   g_is32;

__device__ __forceinline__ uint32_t packbf(float lo16, float hi16) {
    uint32_t r;
    asm("cvt.rn.bf16x2.f32 %0, %1, %2;" : "=r"(r) : "f"(hi16), "f"(lo16));
    return r;
}
__device__ __forceinline__ void mma_bf16(float* c, const uint32_t* a, const uint32_t* b) {
    asm volatile(
        "mma.sync.aligned.m16n8k16.row.col.f32.bf16.bf16.f32 "
        "{%0,%1,%2,%3}, {%4,%5,%6,%7}, {%8,%9}, {%0,%1,%2,%3};"
        : "+f"(c[0]), "+f"(c[1]), "+f"(c[2]), "+f"(c[3])
        : "r"(a[0]), "r"(a[1]), "r"(a[2]), "r"(a[3]), "r"(b[0]), "r"(b[1]));
}

// -------- zero + edge dtype sniffer (merged) --------------------------------
__global__ void k_zero(const long long* __restrict__ e, long long E, long long N) {
    int i = blockIdx.x * blockDim.x + threadIdx.x;
    if (i < (int)N) g_cnt[i] = 0;
    if (blockIdx.x == 0 && threadIdx.x == 0) {
        int is32 = 0;
        long long cnt = E < 256 ? E : 256;
        for (long long j = 0; j < cnt; j++) {
            long long v = e[j];
            if (v < 0 || v >= N) { is32 = 1; break; }
        }
        g_is32 = is32;
    }
}

// -------- CSR histogram -----------------------------------------------------
__global__ void k_hist(const void* __restrict__ ei, long long E, int N) {
    long long i = (long long)blockIdx.x * blockDim.x + threadIdx.x;
    long long EN = E + (long long)N;
    if (i >= EN) return;
    int d;
    if (i >= E) d = (int)(i - E);
    else if (g_is32) d = ((const int*)ei)[E + i];
    else             d = (int)((const long long*)ei)[E + i];
    atomicAdd(&g_cnt[d], 1);
}

// -------- scan level 1 ------------------------------------------------------
__global__ void k_scan1(int N) {
    __shared__ int sh[SCANB];
    int t = threadIdx.x;
    int i = blockIdx.x * SCANB + t;
    int v = (i < N) ? g_cnt[i] : 0;
    sh[t] = v;
    __syncthreads();
    #pragma unroll
    for (int o = 1; o < SCANB; o <<= 1) {
        int u = (t >= o) ? sh[t - o] : 0;
        __syncthreads();
        sh[t] += u;
        __syncthreads();
    }
    if (i < N) g_off[i] = sh[t] - v;
    if (t == SCANB - 1) g_bsum[blockIdx.x] = sh[t];
}

// -------- scan level 2+3 merged ---------------------------------------------
__global__ void k_scan3(int N, int total, int nb) {
    __shared__ int sh[SCANB];
    int t = threadIdx.x;
    int v = (t < nb && t < blockIdx.x) ? g_bsum[t] : 0;
    sh[t] = v;
    __syncthreads();
    #pragma unroll
    for (int o = SCANB / 2; o; o >>= 1) {
        if (t < o) sh[t] += sh[t + o];
        __syncthreads();
    }
    int base = sh[0];
    int i = blockIdx.x * SCANB + t;
    if (i < N) {
        int o = g_off[i] + base;
        g_off[i] = o;
        g_cur[i] = o;
    }
    if (i == 0) g_off[N] = total;
}

// -------- CSR scatter -------------------------------------------------------
__global__ void k_scatter(const void* __restrict__ ei, long long E, int N) {
    long long i = (long long)blockIdx.x * blockDim.x + threadIdx.x;
    long long EN = E + (long long)N;
    if (i >= EN) return;
    int s, d;
    if (i >= E) { s = d = (int)(i - E); }
    else if (g_is32) { const int* p = (const int*)ei; s = p[i]; d = p[E + i]; }
    else { const long long* p = (const long long*)ei; s = (int)p[i]; d = (int)p[E + i]; }
    int pos = atomicAdd(&g_cur[d], 1);
    g_csr[pos] = s;
}

// -------- GEMM1 (tensor cores): split-bf16, double-buffered, alpha1 fused ---
__global__ void k_gemm1(const float* __restrict__ x, const float* __restrict__ W,
                        const float* __restrict__ a_src, const float* __restrict__ a_dst,
                        int N) {
    __shared__ uint32_t Ahi[128][20], Alo[128][20];
    __shared__ uint32_t Bhi[64][20],  Blo[64][20];
    __shared__ float sA[64], sD[64];

    int tid  = threadIdx.x;
    int lane = tid & 31;
    int warp = tid >> 5;
    int m0   = blockIdx.x * 128;
    int wrow = warp * 16;
    int g = lane >> 2, tg = lane & 3;

    if (tid < 64) { sA[tid] = a_src[tid]; sD[tid] = a_dst[tid]; }

    float c[8][4] = {};

    float4 vc[4];
    #pragma unroll
    for (int it = 0; it < 4; it++) {
        int f = tid + 256 * it, row = f >> 3, c4 = f & 7;
        vc[it] = make_float4(0.f, 0.f, 0.f, 0.f);
        if (m0 + row < N)
            vc[it] = *(const float4*)&x[(long long)(m0 + row) * FF + c4 * 4];
    }
    int wj = tid >> 4, wn4 = tid & 15;
    float4 wc0 = *(const float4*)&W[(2 * wj)     * 64 + wn4 * 4];
    float4 wc1 = *(const float4*)&W[(2 * wj + 1) * 64 + wn4 * 4];

    for (int kk = 0; kk < FF; kk += 32) {
        __syncthreads();
        #pragma unroll
        for (int it = 0; it < 4; it++) {
            int f = tid + 256 * it, row = f >> 3, c4 = f & 7;
            float4 v = vc[it];
            float hx = __bfloat162float(__float2bfloat16(v.x));
            float hy = __bfloat162float(__float2bfloat16(v.y));
            float hz = __bfloat162float(__float2bfloat16(v.z));
            float hw = __bfloat162float(__float2bfloat16(v.w));
            Ahi[row][c4*2+0] = packbf(hx, hy);
            Ahi[row][c4*2+1] = packbf(hz, hw);
            Alo[row][c4*2+0] = packbf(v.x - hx, v.y - hy);
            Alo[row][c4*2+1] = packbf(v.z - hz, v.w - hw);
        }
        {
            const float e0[4] = {wc0.x, wc0.y, wc0.z, wc0.w};
            const float e1[4] = {wc1.x, wc1.y, wc1.z, wc1.w};
            #pragma unroll
            for (int i = 0; i < 4; i++) {
                float h0 = __bfloat162float(__float2bfloat16(e0[i]));
                float h1 = __bfloat162float(__float2bfloat16(e1[i]));
                Bhi[wn4*4 + i][wj] = packbf(h0, h1);
                Blo[wn4*4 + i][wj] = packbf(e0[i] - h0, e1[i] - h1);
            }
        }
        __syncthreads();
        float4 vn[4], wn0, wn1;
        bool more = (kk + 32 < FF);
        if (more) {
            #pragma unroll
            for (int it = 0; it < 4; it++) {
                int f = tid + 256 * it, row = f >> 3, c4 = f & 7;
                vn[it] = make_float4(0.f, 0.f, 0.f, 0.f);
                if (m0 + row < N)
                    vn[it] = *(const float4*)&x[(long long)(m0 + row) * FF + kk + 32 + c4 * 4];
            }
            wn0 = *(const float4*)&W[(kk + 32 + 2 * wj)     * 64 + wn4 * 4];
            wn1 = *(const float4*)&W[(kk + 32 + 2 * wj + 1) * 64 + wn4 * 4];
        }
        #pragma unroll
        for (int sub = 0; sub < 2; sub++) {
            int po = sub * 8;
            uint32_t ah[4], al[4];
            ah[0] = Ahi[wrow + g    ][po + tg];
            ah[1] = Ahi[wrow + g + 8][po + tg];
            ah[2] = Ahi[wrow + g    ][po + tg + 4];
            ah[3] = Ahi[wrow + g + 8][po + tg + 4];
            al[0] = Alo[wrow + g    ][po + tg];
            al[1] = Alo[wrow + g + 8][po + tg];
            al[2] = Alo[wrow + g    ][po + tg + 4];
            al[3] = Alo[wrow + g + 8][po + tg + 4];
            #pragma unroll
            for (int t = 0; t < 8; t++) {
                uint32_t bh[2], bl[2];
                bh[0] = Bhi[t*8 + g][po + tg];
                bh[1] = Bhi[t*8 + g][po + tg + 4];
                bl[0] = Blo[t*8 + g][po + tg];
                bl[1] = Blo[t*8 + g][po + tg + 4];
                mma_bf16(c[t], ah, bh);
                mma_bf16(c[t], ah, bl);
                mma_bf16(c[t], al, bh);
            }
        }
        if (more) {
            #pragma unroll
            for (int it = 0; it < 4; it++) vc[it] = vn[it];
            wc0 = wn0; wc1 = wn1;
        }
    }

    int row0 = m0 + wrow + g;
    int row1 = row0 + 8;
    #pragma unroll
    for (int t = 0; t < 8; t++) {
        if (row0 < N)
            *(float2*)&g_h1[row0 * 64 + t*8 + tg*2] = make_float2(c[t][0], c[t][1]);
        if (row1 < N)
            *(float2*)&g_h1[row1 * 64 + t*8 + tg*2] = make_float2(c[t][2], c[t][3]);
        float as = sA[t*8 + tg*2], as2v = sA[t*8 + tg*2 + 1];
        float ad = sD[t*8 + tg*2], ad2v = sD[t*8 + tg*2 + 1];
        float s0 = c[t][0]*as + c[t][1]*as2v;
        float d0 = c[t][0]*ad + c[t][1]*ad2v;
        float s1 = c[t][2]*as + c[t][3]*as2v;
        float d1 = c[t][2]*ad + c[t][3]*ad2v;
        #pragma unroll
        for (int o = 1; o <= 2; o <<= 1) {
            s0 += __shfl_xor_sync(0xffffffffu, s0, o);
            d0 += __shfl_xor_sync(0xffffffffu, d0, o);
            s1 += __shfl_xor_sync(0xffffffffu, s1, o);
            d1 += __shfl_xor_sync(0xffffffffu, d1, o);
        }
        if (tg == 0) {
            if (row0 < N) { g_as1[row0 * 8 + t] = s0; g_ad1[row0 * 8 + t] = d0; }
            if (row1 < N) { g_as1[row1 * 8 + t] = s1; g_ad1[row1 * 8 + t] = d1; }
        }
    }
}

// -------- agg layer 1 + GEMM2 + alpha2, fused; FULL payload pipeline --------
// Warp per dst. Index AND payload (as1, h1) prefetched one edge ahead so
// every L2 gather gets a loop-body head start. +4 live regs in the loop.
__global__ void k_agg1(const float* __restrict__ b1,
                       const float* __restrict__ W2,
                       const float* __restrict__ a_src2,
                       const float* __restrict__ a_dst2, int N) {
    __shared__ float sW2[HD * NC];    // 2.5 KB, [f*10+c]
    __shared__ float sAs2[NC], sAd2[NC], sB1[HD];
    int tid = threadIdx.x;
    for (int i = tid; i < HD * NC; i += blockDim.x) sW2[i] = W2[i];
    if (tid < NC) { sAs2[tid] = a_src2[tid]; sAd2[tid] = a_dst2[tid]; }
    if (tid < HD) sB1[tid] = b1[tid];
    __syncthreads();

    int d = (blockIdx.x * blockDim.x + tid) >> 5;
    int lane = tid & 31;
    if (d >= N) return;
    int beg = g_off[d], end = g_off[d + 1];
    float ad_l = (lane < NH) ? g_ad1[d * NH + lane] : 0.f;
    float accx = 0.f, accy = 0.f, den = 0.f;

    // stage 0: first index + payload
    int s = (beg < end) ? g_csr[beg] : 0;
    float  a1 = (lane < NH) ? g_as1[s * NH + lane] : 0.f;
    float2 hv = *(const float2*)&g_h1[s * 64 + lane * 2];

    for (int i = beg; i < end; i++) {
        // prefetch next edge's index and payload (tail reads idx 0: benign)
        int sn = (i + 1 < end) ? g_csr[i + 1] : 0;
        float  a1n = (lane < NH) ? g_as1[sn * NH + lane] : 0.f;
        float2 hvn = *(const float2*)&g_h1[sn * 64 + lane * 2];
        // compute with current payload
        float w = 0.f;
        if (lane < NH) {
            float e = a1 + ad_l;
            e = e > 0.f ? e : 0.2f * e;
            w = __expf(e);
            den += w;
        }
        float wl = __shfl_sync(0xffffffffu, w, lane >> 2);
        accx += wl * hv.x;
        accy += wl * hv.y;
        s = sn; a1 = a1n; hv = hvn;
    }
    float denl = __shfl_sync(0xffffffffu, den, lane >> 2);
    float v0 = accx / denl + sB1[2 * lane];
    float v1 = accy / denl + sB1[2 * lane + 1];
    v0 = v0 > 0.f ? v0 : expm1f(v0);   // ELU
    v1 = v1 > 0.f ? v1 : expm1f(v1);

    // fused 64->10 projection + alpha2
    float asum = 0.f, adsum = 0.f;
    #pragma unroll
    for (int c = 0; c < NC; c++) {
        float sacc = v0 * sW2[(2 * lane) * NC + c] + v1 * sW2[(2 * lane + 1) * NC + c];
        #pragma unroll
        for (int o = 16; o; o >>= 1) sacc += __shfl_down_sync(0xffffffffu, sacc, o);
        if (lane == 0) {
            g_h2p[d * 12 + c] = sacc;
            asum  += sacc * sAs2[c];
            adsum += sacc * sAd2[c];
        }
    }
    if (lane == 0) {
        g_h2p[d * 12 + 10] = asum;
        g_h2p[d * 12 + 11] = 0.f;
        g_ad2[d] = adsum;
    }
}

// -------- aggregation layer 2: record payload pipelined ----------------------
__global__ void k_agg2(const float* __restrict__ b2, float* __restrict__ out, int N) {
    int d = (blockIdx.x * blockDim.x + threadIdx.x) >> 5;
    int lane = threadIdx.x & 31;
    if (d >= N) return;
    int beg = g_off[d], end = g_off[d + 1];
    float ad_d = g_ad2[d];
    float acc[NC] = {};
    float den = 0.f;

    int i = beg + lane;
    int s = (i < end) ? g_csr[i] : 0;
    const float4* rp = (const float4*)&g_h2p[s * 12];
    float4 f0 = rp[0], f1 = rp[1], f2 = rp[2];

    for (; i < end; i += 32) {
        int sn = (i + 32 < end) ? g_csr[i + 32] : 0;
        const float4* rpn = (const float4*)&g_h2p[sn * 12];
        float4 n0 = rpn[0], n1 = rpn[1], n2 = rpn[2];   // prefetch next record
        float e = f2.z + ad_d;                 // f2.z = a_src2 . h2[s]
        e = e > 0.f ? e : 0.2f * e;
        float w = __expf(e);
        den += w;
        acc[0] += w * f0.x; acc[1] += w * f0.y; acc[2] += w * f0.z; acc[3] += w * f0.w;
        acc[4] += w * f1.x; acc[5] += w * f1.y; acc[6] += w * f1.z; acc[7] += w * f1.w;
        acc[8] += w * f2.x; acc[9] += w * f2.y;
        f0 = n0; f1 = n1; f2 = n2;
    }
    #pragma unroll
    for (int o = 16; o; o >>= 1) {
        den += __shfl_down_sync(0xffffffffu, den, o);
        #pragma unroll
        for (int c = 0; c < NC; c++)
            acc[c] += __shfl_down_sync(0xffffffffu, acc[c], o);
    }
    if (lane == 0) {
        float inv = 1.f / den;
        float v[NC], m = -1e30f;
        #pragma unroll
        for (int c = 0; c < NC; c++) {
            v[c] = acc[c] * inv + b2[c];
            m = fmaxf(m, v[c]);
        }
        float ssum = 0.f;
        #pragma unroll
        for (int c = 0; c < NC; c++) ssum += __expf(v[c] - m);
        float l = __logf(ssum);
        #pragma unroll
        for (int c = 0; c < NC; c++) out[d * NC + c] = v[c] - m - l;
    }
}

// ---------------------------------------------------------------------------
extern "C" void kernel_launch(void* const* d_in, const int* in_sizes, int n_in,
                              void* d_out, int out_size) {
    const float* x   = (const float*)d_in[0];
    const void*  ei  = d_in[1];
    const float* W1  = (const float*)d_in[2];
    const float* as1 = (const float*)d_in[3];
    const float* ad1 = (const float*)d_in[4];
    const float* b1  = (const float*)d_in[5];
    const float* W2  = (const float*)d_in[6];
    const float* as2 = (const float*)d_in[7];
    const float* ad2 = (const float*)d_in[8];
    const float* b2  = (const float*)d_in[9];

    int       N  = in_sizes[0] / FF;
    long long E  = (long long)in_sizes[1] / 2;
    long long EN = E + (long long)N;
    int nb = (N + SCANB - 1) / SCANB;
    float* out = (float*)d_out;

    cudaStream_t s1 = 0;
    cudaEvent_t ev0 = 0, ev1 = 0;
    bool forked =
        cudaStreamCreateWithFlags(&s1, cudaStreamNonBlocking) == cudaSuccess &&
        cudaEventCreateWithFlags(&ev0, cudaEventDisableTiming) == cudaSuccess &&
        cudaEventCreateWithFlags(&ev1, cudaEventDisableTiming) == cudaSuccess;

    if (forked) forked = cudaEventRecord(ev0, 0) == cudaSuccess &&
                         cudaStreamWaitEvent(s1, ev0, 0) == cudaSuccess;

    cudaStream_t cs = forked ? s1 : 0;

    // ---- branch A: CSR build (edge_index only) ----
    k_zero<<<(N + 255) / 256, 256, 0, cs>>>((const long long*)ei, E, N);
    k_hist<<<(unsigned)((EN + 255) / 256), 256, 0, cs>>>(ei, E, N);
    k_scan1<<<nb, SCANB, 0, cs>>>(N);
    k_scan3<<<nb, SCANB, 0, cs>>>(N, (int)EN, nb);
    k_scatter<<<(unsigned)((EN + 255) / 256), 256, 0, cs>>>(ei, E, N);
    if (forked) forked = cudaEventRecord(ev1, s1) == cudaSuccess;

    // ---- branch B: projection GEMM (x, W1 only) ----
    k_gemm1<<<(N + 127) / 128, 256>>>(x, W1, as1, ad1, N);

    // ---- join + tail ----
    if (forked) cudaStreamWaitEvent(0, ev1, 0);

    k_agg1<<<(unsigned)(((long long)N * 32 + 255) / 256), 256>>>(b1, W2, as2, ad2, N);
    k_agg2<<<(unsigned)(((long long)N * 32 + 255) / 256), 256>>>(b2, out, N);
    // Streams/events intentionally not destroyed (illegal mid-capture;
    // host-side handles only, O(1) calls, no device memory involved).
}

// round 15
// speedup vs baseline: 1.2987x; 1.2987x over previous
#include <cuda_runtime.h>
#include <cuda_bf16.h>
#include <cstdint>

#define FF  512
#define HD  64
#define NH  8
#define NC  10
#define NMAX 50000
#define EMAX 1700000
#define SCANB 256
#define NBMAX ((NMAX + SCANB - 1) / SCANB)

// -------- scratch (static device globals; no allocation allowed) ----------
static __device__ float g_h1  [NMAX*HD];
static __device__ float g_as1 [NMAX*NH];
static __device__ float g_ad1 [NMAX*NH];
static __device__ float g_h2p [NMAX*12];   // h2[0..9], slot10 = a_src2·h2
static __device__ float g_ad2 [NMAX];
static __device__ int   g_cnt [NMAX];
static __device__ int   g_off [NMAX+1];
static __device__ int   g_cur [NMAX];
static __device__ int   g_csr [EMAX];
static __device__ int   g_bsum[NBMAX];
static __device__ int   g_is32;

__device__ __forceinline__ uint32_t packbf(float lo16, float hi16) {
    uint32_t r;
    asm("cvt.rn.bf16x2.f32 %0, %1, %2;" : "=r"(r) : "f"(hi16), "f"(lo16));
    return r;
}
__device__ __forceinline__ void mma_bf16(float* c, const uint32_t* a, const uint32_t* b) {
    asm volatile(
        "mma.sync.aligned.m16n8k16.row.col.f32.bf16.bf16.f32 "
        "{%0,%1,%2,%3}, {%4,%5,%6,%7}, {%8,%9}, {%0,%1,%2,%3};"
        : "+f"(c[0]), "+f"(c[1]), "+f"(c[2]), "+f"(c[3])
        : "r"(a[0]), "r"(a[1]), "r"(a[2]), "r"(a[3]), "r"(b[0]), "r"(b[1]));
}

// -------- zero + edge dtype sniffer (merged) --------------------------------
__global__ void k_zero(const long long* __restrict__ e, long long E, long long N) {
    int i = blockIdx.x * blockDim.x + threadIdx.x;
    if (i < (int)N) g_cnt[i] = 0;
    if (blockIdx.x == 0 && threadIdx.x == 0) {
        int is32 = 0;
        long long cnt = E < 256 ? E : 256;
        for (long long j = 0; j < cnt; j++) {
            long long v = e[j];
            if (v < 0 || v >= N) { is32 = 1; break; }
        }
        g_is32 = is32;
    }
}

// -------- CSR histogram -----------------------------------------------------
__global__ void k_hist(const void* __restrict__ ei, long long E, int N) {
    long long i = (long long)blockIdx.x * blockDim.x + threadIdx.x;
    long long EN = E + (long long)N;
    if (i >= EN) return;
    int d;
    if (i >= E) d = (int)(i - E);
    else if (g_is32) d = ((const int*)ei)[E + i];
    else             d = (int)((const long long*)ei)[E + i];
    atomicAdd(&g_cnt[d], 1);
}

// -------- scan level 1 ------------------------------------------------------
__global__ void k_scan1(int N) {
    __shared__ int sh[SCANB];
    int t = threadIdx.x;
    int i = blockIdx.x * SCANB + t;
    int v = (i < N) ? g_cnt[i] : 0;
    sh[t] = v;
    __syncthreads();
    #pragma unroll
    for (int o = 1; o < SCANB; o <<= 1) {
        int u = (t >= o) ? sh[t - o] : 0;
        __syncthreads();
        sh[t] += u;
        __syncthreads();
    }
    if (i < N) g_off[i] = sh[t] - v;
    if (t == SCANB - 1) g_bsum[blockIdx.x] = sh[t];
}

// -------- scan level 2+3 merged ---------------------------------------------
__global__ void k_scan3(int N, int total, int nb) {
    __shared__ int sh[SCANB];
    int t = threadIdx.x;
    int v = (t < nb && t < blockIdx.x) ? g_bsum[t] : 0;
    sh[t] = v;
    __syncthreads();
    #pragma unroll
    for (int o = SCANB / 2; o; o >>= 1) {
        if (t < o) sh[t] += sh[t + o];
        __syncthreads();
    }
    int base = sh[0];
    int i = blockIdx.x * SCANB + t;
    if (i < N) {
        int o = g_off[i] + base;
        g_off[i] = o;
        g_cur[i] = o;
    }
    if (i == 0) g_off[N] = total;
}

// -------- CSR scatter -------------------------------------------------------
__global__ void k_scatter(const void* __restrict__ ei, long long E, int N) {
    long long i = (long long)blockIdx.x * blockDim.x + threadIdx.x;
    long long EN = E + (long long)N;
    if (i >= EN) return;
    int s, d;
    if (i >= E) { s = d = (int)(i - E); }
    else if (g_is32) { const int* p = (const int*)ei; s = p[i]; d = p[E + i]; }
    else { const long long* p = (const long long*)ei; s = (int)p[i]; d = (int)p[E + i]; }
    int pos = atomicAdd(&g_cur[d], 1);
    g_csr[pos] = s;
}

// -------- GEMM1 (tensor cores): split-bf16, double-buffered, alpha1 fused ---
__global__ void k_gemm1(const float* __restrict__ x, const float* __restrict__ W,
                        const float* __restrict__ a_src, const float* __restrict__ a_dst,
                        int N) {
    __shared__ uint32_t Ahi[128][20], Alo[128][20];
    __shared__ uint32_t Bhi[64][20],  Blo[64][20];
    __shared__ float sA[64], sD[64];

    int tid  = threadIdx.x;
    int lane = tid & 31;
    int warp = tid >> 5;
    int m0   = blockIdx.x * 128;
    int wrow = warp * 16;
    int g = lane >> 2, tg = lane & 3;

    if (tid < 64) { sA[tid] = a_src[tid]; sD[tid] = a_dst[tid]; }

    float c[8][4] = {};

    float4 vc[4];
    #pragma unroll
    for (int it = 0; it < 4; it++) {
        int f = tid + 256 * it, row = f >> 3, c4 = f & 7;
        vc[it] = make_float4(0.f, 0.f, 0.f, 0.f);
        if (m0 + row < N)
            vc[it] = *(const float4*)&x[(long long)(m0 + row) * FF + c4 * 4];
    }
    int wj = tid >> 4, wn4 = tid & 15;
    float4 wc0 = *(const float4*)&W[(2 * wj)     * 64 + wn4 * 4];
    float4 wc1 = *(const float4*)&W[(2 * wj + 1) * 64 + wn4 * 4];

    for (int kk = 0; kk < FF; kk += 32) {
        __syncthreads();
        #pragma unroll
        for (int it = 0; it < 4; it++) {
            int f = tid + 256 * it, row = f >> 3, c4 = f & 7;
            float4 v = vc[it];
            float hx = __bfloat162float(__float2bfloat16(v.x));
            float hy = __bfloat162float(__float2bfloat16(v.y));
            float hz = __bfloat162float(__float2bfloat16(v.z));
            float hw = __bfloat162float(__float2bfloat16(v.w));
            Ahi[row][c4*2+0] = packbf(hx, hy);
            Ahi[row][c4*2+1] = packbf(hz, hw);
            Alo[row][c4*2+0] = packbf(v.x - hx, v.y - hy);
            Alo[row][c4*2+1] = packbf(v.z - hz, v.w - hw);
        }
        {
            const float e0[4] = {wc0.x, wc0.y, wc0.z, wc0.w};
            const float e1[4] = {wc1.x, wc1.y, wc1.z, wc1.w};
            #pragma unroll
            for (int i = 0; i < 4; i++) {
                float h0 = __bfloat162float(__float2bfloat16(e0[i]));
                float h1 = __bfloat162float(__float2bfloat16(e1[i]));
                Bhi[wn4*4 + i][wj] = packbf(h0, h1);
                Blo[wn4*4 + i][wj] = packbf(e0[i] - h0, e1[i] - h1);
            }
        }
        __syncthreads();
        float4 vn[4], wn0, wn1;
        bool more = (kk + 32 < FF);
        if (more) {
            #pragma unroll
            for (int it = 0; it < 4; it++) {
                int f = tid + 256 * it, row = f >> 3, c4 = f & 7;
                vn[it] = make_float4(0.f, 0.f, 0.f, 0.f);
                if (m0 + row < N)
                    vn[it] = *(const float4*)&x[(long long)(m0 + row) * FF + kk + 32 + c4 * 4];
            }
            wn0 = *(const float4*)&W[(kk + 32 + 2 * wj)     * 64 + wn4 * 4];
            wn1 = *(const float4*)&W[(kk + 32 + 2 * wj + 1) * 64 + wn4 * 4];
        }
        #pragma unroll
        for (int sub = 0; sub < 2; sub++) {
            int po = sub * 8;
            uint32_t ah[4], al[4];
            ah[0] = Ahi[wrow + g    ][po + tg];
            ah[1] = Ahi[wrow + g + 8][po + tg];
            ah[2] = Ahi[wrow + g    ][po + tg + 4];
            ah[3] = Ahi[wrow + g + 8][po + tg + 4];
            al[0] = Alo[wrow + g    ][po + tg];
            al[1] = Alo[wrow + g + 8][po + tg];
            al[2] = Alo[wrow + g    ][po + tg + 4];
            al[3] = Alo[wrow + g + 8][po + tg + 4];
            #pragma unroll
            for (int t = 0; t < 8; t++) {
                uint32_t bh[2], bl[2];
                bh[0] = Bhi[t*8 + g][po + tg];
                bh[1] = Bhi[t*8 + g][po + tg + 4];
                bl[0] = Blo[t*8 + g][po + tg];
                bl[1] = Blo[t*8 + g][po + tg + 4];
                mma_bf16(c[t], ah, bh);
                mma_bf16(c[t], ah, bl);
                mma_bf16(c[t], al, bh);
            }
        }
        if (more) {
            #pragma unroll
            for (int it = 0; it < 4; it++) vc[it] = vn[it];
            wc0 = wn0; wc1 = wn1;
        }
    }

    int row0 = m0 + wrow + g;
    int row1 = row0 + 8;
    #pragma unroll
    for (int t = 0; t < 8; t++) {
        if (row0 < N)
            *(float2*)&g_h1[row0 * 64 + t*8 + tg*2] = make_float2(c[t][0], c[t][1]);
        if (row1 < N)
            *(float2*)&g_h1[row1 * 64 + t*8 + tg*2] = make_float2(c[t][2], c[t][3]);
        float as = sA[t*8 + tg*2], as2v = sA[t*8 + tg*2 + 1];
        float ad = sD[t*8 + tg*2], ad2v = sD[t*8 + tg*2 + 1];
        float s0 = c[t][0]*as + c[t][1]*as2v;
        float d0 = c[t][0]*ad + c[t][1]*ad2v;
        float s1 = c[t][2]*as + c[t][3]*as2v;
        float d1 = c[t][2]*ad + c[t][3]*ad2v;
        #pragma unroll
        for (int o = 1; o <= 2; o <<= 1) {
            s0 += __shfl_xor_sync(0xffffffffu, s0, o);
            d0 += __shfl_xor_sync(0xffffffffu, d0, o);
            s1 += __shfl_xor_sync(0xffffffffu, s1, o);
            d1 += __shfl_xor_sync(0xffffffffu, d1, o);
        }
        if (tg == 0) {
            if (row0 < N) { g_as1[row0 * 8 + t] = s0; g_ad1[row0 * 8 + t] = d0; }
            if (row1 < N) { g_as1[row1 * 8 + t] = s1; g_ad1[row1 * 8 + t] = d1; }
        }
    }
}

// -------- agg layer 1 + GEMM2 + alpha2, fused; DUAL-DST warps ---------------
// Each warp handles two dst nodes: two fully independent gather chains per
// iteration -> 2x memory-level parallelism without lengthening any chain.
// Out-of-range chain reads csr index 0 with weight forced to 0 (branch-free).
__global__ void k_agg1(const float* __restrict__ b1,
                       const float* __restrict__ W2,
                       const float* __restrict__ a_src2,
                       const float* __restrict__ a_dst2, int N) {
    __shared__ float sW2[HD * NC];    // 2.5 KB, [f*10+c]
    __shared__ float sAs2[NC], sAd2[NC], sB1[HD];
    int tid = threadIdx.x;
    for (int i = tid; i < HD * NC; i += blockDim.x) sW2[i] = W2[i];
    if (tid < NC) { sAs2[tid] = a_src2[tid]; sAd2[tid] = a_dst2[tid]; }
    if (tid < HD) sB1[tid] = b1[tid];
    __syncthreads();

    int wid = (blockIdx.x * blockDim.x + tid) >> 5;
    int lane = tid & 31;
    int d0 = wid * 2, d1 = wid * 2 + 1;
    if (d0 >= N) return;
    bool has1 = (d1 < N);

    int b0 = g_off[d0], e0 = g_off[d0 + 1];
    int b1o = has1 ? g_off[d1] : 0, e1 = has1 ? g_off[d1 + 1] : 0;
    int L0 = e0 - b0, L1 = e1 - b1o;
    float ad0 = (lane < NH) ? g_ad1[d0 * NH + lane] : 0.f;
    float ad1 = (lane < NH && has1) ? g_ad1[d1 * NH + lane] : 0.f;

    float ax0 = 0.f, ay0 = 0.f, dn0 = 0.f;
    float ax1 = 0.f, ay1 = 0.f, dn1 = 0.f;
    int n = L0 > L1 ? L0 : L1;
    for (int j = 0; j < n; j++) {
        int s0 = (j < L0) ? g_csr[b0 + j]  : 0;   // two independent chains
        int s1 = (j < L1) ? g_csr[b1o + j] : 0;
        float w0 = 0.f, w1 = 0.f;
        if (lane < NH) {
            float q0 = g_as1[s0 * NH + lane] + ad0;
            q0 = q0 > 0.f ? q0 : 0.2f * q0;
            w0 = (j < L0) ? __expf(q0) : 0.f;
            dn0 += w0;
            float q1 = g_as1[s1 * NH + lane] + ad1;
            q1 = q1 > 0.f ? q1 : 0.2f * q1;
            w1 = (j < L1) ? __expf(q1) : 0.f;
            dn1 += w1;
        }
        float wl0 = __shfl_sync(0xffffffffu, w0, lane >> 2);
        float wl1 = __shfl_sync(0xffffffffu, w1, lane >> 2);
        float2 h0 = *(const float2*)&g_h1[s0 * 64 + lane * 2];
        float2 h1v = *(const float2*)&g_h1[s1 * 64 + lane * 2];
        ax0 += wl0 * h0.x;  ay0 += wl0 * h0.y;
        ax1 += wl1 * h1v.x; ay1 += wl1 * h1v.y;
    }

    // epilogue per dst: normalize + bias + ELU + fused 64->10 + alpha2
    #pragma unroll
    for (int q = 0; q < 2; q++) {
        int d = q ? d1 : d0;
        if (q && !has1) break;
        float dnl = __shfl_sync(0xffffffffu, q ? dn1 : dn0, lane >> 2);
        float v0 = (q ? ax1 : ax0) / dnl + sB1[2 * lane];
        float v1 = (q ? ay1 : ay0) / dnl + sB1[2 * lane + 1];
        v0 = v0 > 0.f ? v0 : expm1f(v0);   // ELU
        v1 = v1 > 0.f ? v1 : expm1f(v1);
        float asum = 0.f, adsum = 0.f;
        #pragma unroll
        for (int c = 0; c < NC; c++) {
            float sacc = v0 * sW2[(2 * lane) * NC + c] + v1 * sW2[(2 * lane + 1) * NC + c];
            #pragma unroll
            for (int o = 16; o; o >>= 1) sacc += __shfl_down_sync(0xffffffffu, sacc, o);
            if (lane == 0) {
                g_h2p[d * 12 + c] = sacc;
                asum  += sacc * sAs2[c];
                adsum += sacc * sAd2[c];
            }
        }
        if (lane == 0) {
            g_h2p[d * 12 + 10] = asum;
            g_h2p[d * 12 + 11] = 0.f;
            g_ad2[d] = adsum;
        }
    }
}

// -------- aggregation layer 2 (R13 version: 3x LDG.128/edge, idx pipelined) --
__global__ void k_agg2(const float* __restrict__ b2, float* __restrict__ out, int N) {
    int d = (blockIdx.x * blockDim.x + threadIdx.x) >> 5;
    int lane = threadIdx.x & 31;
    if (d >= N) return;
    int beg = g_off[d], end = g_off[d + 1];
    float ad_d = g_ad2[d];
    float acc[NC] = {};
    float den = 0.f;
    int i = beg + lane;
    int s = (i < end) ? g_csr[i] : 0;
    for (; i < end; i += 32) {
        int snext = (i + 32 < end) ? g_csr[i + 32] : 0;
        const float4* rp = (const float4*)&g_h2p[s * 12];
        float4 f0 = rp[0], f1 = rp[1], f2 = rp[2];
        float e = f2.z + ad_d;                 // f2.z = a_src2 . h2[s]
        e = e > 0.f ? e : 0.2f * e;
        float w = __expf(e);
        den += w;
        acc[0] += w * f0.x; acc[1] += w * f0.y; acc[2] += w * f0.z; acc[3] += w * f0.w;
        acc[4] += w * f1.x; acc[5] += w * f1.y; acc[6] += w * f1.z; acc[7] += w * f1.w;
        acc[8] += w * f2.x; acc[9] += w * f2.y;
        s = snext;
    }
    #pragma unroll
    for (int o = 16; o; o >>= 1) {
        den += __shfl_down_sync(0xffffffffu, den, o);
        #pragma unroll
        for (int c = 0; c < NC; c++)
            acc[c] += __shfl_down_sync(0xffffffffu, acc[c], o);
    }
    if (lane == 0) {
        float inv = 1.f / den;
        float v[NC], m = -1e30f;
        #pragma unroll
        for (int c = 0; c < NC; c++) {
            v[c] = acc[c] * inv + b2[c];
            m = fmaxf(m, v[c]);
        }
        float ssum = 0.f;
        #pragma unroll
        for (int c = 0; c < NC; c++) ssum += __expf(v[c] - m);
        float l = __logf(ssum);
        #pragma unroll
        for (int c = 0; c < NC; c++) out[d * NC + c] = v[c] - m - l;
    }
}

// ---------------------------------------------------------------------------
extern "C" void kernel_launch(void* const* d_in, const int* in_sizes, int n_in,
                              void* d_out, int out_size) {
    const float* x   = (const float*)d_in[0];
    const void*  ei  = d_in[1];
    const float* W1  = (const float*)d_in[2];
    const float* as1 = (const float*)d_in[3];
    const float* ad1 = (const float*)d_in[4];
    const float* b1  = (const float*)d_in[5];
    const float* W2  = (const float*)d_in[6];
    const float* as2 = (const float*)d_in[7];
    const float* ad2 = (const float*)d_in[8];
    const float* b2  = (const float*)d_in[9];

    int       N  = in_sizes[0] / FF;
    long long E  = (long long)in_sizes[1] / 2;
    long long EN = E + (long long)N;
    int nb = (N + SCANB - 1) / SCANB;
    int npairs = (N + 1) / 2;
    float* out = (float*)d_out;

    cudaStream_t s1 = 0;
    cudaEvent_t ev0 = 0, ev1 = 0;
    bool forked =
        cudaStreamCreateWithFlags(&s1, cudaStreamNonBlocking) == cudaSuccess &&
        cudaEventCreateWithFlags(&ev0, cudaEventDisableTiming) == cudaSuccess &&
        cudaEventCreateWithFlags(&ev1, cudaEventDisableTiming) == cudaSuccess;

    if (forked) forked = cudaEventRecord(ev0, 0) == cudaSuccess &&
                         cudaStreamWaitEvent(s1, ev0, 0) == cudaSuccess;

    cudaStream_t cs = forked ? s1 : 0;

    // ---- branch A: CSR build (edge_index only) ----
    k_zero<<<(N + 255) / 256, 256, 0, cs>>>((const long long*)ei, E, N);
    k_hist<<<(unsigned)((EN + 255) / 256), 256, 0, cs>>>(ei, E, N);
    k_scan1<<<nb, SCANB, 0, cs>>>(N);
    k_scan3<<<nb, SCANB, 0, cs>>>(N, (int)EN, nb);
    k_scatter<<<(unsigned)((EN + 255) / 256), 256, 0, cs>>>(ei, E, N);
    if (forked) forked = cudaEventRecord(ev1, s1) == cudaSuccess;

    // ---- branch B: projection GEMM (x, W1 only) ----
    k_gemm1<<<(N + 127) / 128, 256>>>(x, W1, as1, ad1, N);

    // ---- join + tail ----
    if (forked) cudaStreamWaitEvent(0, ev1, 0);

    k_agg1<<<(unsigned)(((long long)npairs * 32 + 255) / 256), 256>>>(b1, W2, as2, ad2, N);
    k_agg2<<<(unsigned)(((long long)N * 32 + 255) / 256), 256>>>(b2, out, N);
    // Streams/events intentionally not destroyed (illegal mid-capture;
    // host-side handles only, O(1) calls, no device memory involved).
}

// round 16
// speedup vs baseline: 1.4360x; 1.1057x over previous
#include <cuda_runtime.h>
#include <cuda_bf16.h>
#include <cstdint>

#define FF  512
#define HD  64
#define NH  8
#define NC  10
#define NMAX 50000
#define EMAX 1700000
#define SCANB 256
#define NBMAX ((NMAX + SCANB - 1) / SCANB)

// -------- scratch (static device globals; no allocation allowed) ----------
static __device__ float g_h1  [NMAX*HD];
static __device__ float g_as1 [NMAX*NH];
static __device__ float g_ad1 [NMAX*NH];
static __device__ float g_h2p [NMAX*12];   // slot0 = a_src2·h2, slots1..10 = h2
static __device__ float g_ad2 [NMAX];
static __device__ int   g_cnt [NMAX];
static __device__ int   g_off [NMAX+1];
static __device__ int   g_cur [NMAX];
static __device__ int   g_csr [EMAX];
static __device__ int   g_bsum[NBMAX];
static __device__ int   g_is32;

__device__ __forceinline__ uint32_t packbf(float lo16, float hi16) {
    uint32_t r;
    asm("cvt.rn.bf16x2.f32 %0, %1, %2;" : "=r"(r) : "f"(hi16), "f"(lo16));
    return r;
}
__device__ __forceinline__ void mma_bf16(float* c, const uint32_t* a, const uint32_t* b) {
    asm volatile(
        "mma.sync.aligned.m16n8k16.row.col.f32.bf16.bf16.f32 "
        "{%0,%1,%2,%3}, {%4,%5,%6,%7}, {%8,%9}, {%0,%1,%2,%3};"
        : "+f"(c[0]), "+f"(c[1]), "+f"(c[2]), "+f"(c[3])
        : "r"(a[0]), "r"(a[1]), "r"(a[2]), "r"(a[3]), "r"(b[0]), "r"(b[1]));
}

// -------- zero + edge dtype sniffer (merged) --------------------------------
__global__ void k_zero(const long long* __restrict__ e, long long E, long long N) {
    int i = blockIdx.x * blockDim.x + threadIdx.x;
    if (i < (int)N) g_cnt[i] = 0;
    if (blockIdx.x == 0 && threadIdx.x == 0) {
        int is32 = 0;
        long long cnt = E < 256 ? E : 256;
        for (long long j = 0; j < cnt; j++) {
            long long v = e[j];
            if (v < 0 || v >= N) { is32 = 1; break; }
        }
        g_is32 = is32;
    }
}

// -------- CSR histogram -----------------------------------------------------
__global__ void k_hist(const void* __restrict__ ei, long long E, int N) {
    long long i = (long long)blockIdx.x * blockDim.x + threadIdx.x;
    long long EN = E + (long long)N;
    if (i >= EN) return;
    int d;
    if (i >= E) d = (int)(i - E);
    else if (g_is32) d = ((const int*)ei)[E + i];
    else             d = (int)((const long long*)ei)[E + i];
    atomicAdd(&g_cnt[d], 1);
}

// -------- scan level 1 ------------------------------------------------------
__global__ void k_scan1(int N) {
    __shared__ int sh[SCANB];
    int t = threadIdx.x;
    int i = blockIdx.x * SCANB + t;
    int v = (i < N) ? g_cnt[i] : 0;
    sh[t] = v;
    __syncthreads();
    #pragma unroll
    for (int o = 1; o < SCANB; o <<= 1) {
        int u = (t >= o) ? sh[t - o] : 0;
        __syncthreads();
        sh[t] += u;
        __syncthreads();
    }
    if (i < N) g_off[i] = sh[t] - v;
    if (t == SCANB - 1) g_bsum[blockIdx.x] = sh[t];
}

// -------- scan level 2+3 merged ---------------------------------------------
__global__ void k_scan3(int N, int total, int nb) {
    __shared__ int sh[SCANB];
    int t = threadIdx.x;
    int v = (t < nb && t < blockIdx.x) ? g_bsum[t] : 0;
    sh[t] = v;
    __syncthreads();
    #pragma unroll
    for (int o = SCANB / 2; o; o >>= 1) {
        if (t < o) sh[t] += sh[t + o];
        __syncthreads();
    }
    int base = sh[0];
    int i = blockIdx.x * SCANB + t;
    if (i < N) {
        int o = g_off[i] + base;
        g_off[i] = o;
        g_cur[i] = o;
    }
    if (i == 0) g_off[N] = total;
}

// -------- CSR scatter -------------------------------------------------------
__global__ void k_scatter(const void* __restrict__ ei, long long E, int N) {
    long long i = (long long)blockIdx.x * blockDim.x + threadIdx.x;
    long long EN = E + (long long)N;
    if (i >= EN) return;
    int s, d;
    if (i >= E) { s = d = (int)(i - E); }
    else if (g_is32) { const int* p = (const int*)ei; s = p[i]; d = p[E + i]; }
    else { const long long* p = (const long long*)ei; s = (int)p[i]; d = (int)p[E + i]; }
    int pos = atomicAdd(&g_cur[d], 1);
    g_csr[pos] = s;
}

// -------- GEMM1 (tensor cores): split-bf16, double-buffered, alpha1 fused ---
__global__ void k_gemm1(const float* __restrict__ x, const float* __restrict__ W,
                        const float* __restrict__ a_src, const float* __restrict__ a_dst,
                        int N) {
    __shared__ uint32_t Ahi[128][20], Alo[128][20];
    __shared__ uint32_t Bhi[64][20],  Blo[64][20];
    __shared__ float sA[64], sD[64];

    int tid  = threadIdx.x;
    int lane = tid & 31;
    int warp = tid >> 5;
    int m0   = blockIdx.x * 128;
    int wrow = warp * 16;
    int g = lane >> 2, tg = lane & 3;

    if (tid < 64) { sA[tid] = a_src[tid]; sD[tid] = a_dst[tid]; }

    float c[8][4] = {};

    float4 vc[4];
    #pragma unroll
    for (int it = 0; it < 4; it++) {
        int f = tid + 256 * it, row = f >> 3, c4 = f & 7;
        vc[it] = make_float4(0.f, 0.f, 0.f, 0.f);
        if (m0 + row < N)
            vc[it] = *(const float4*)&x[(long long)(m0 + row) * FF + c4 * 4];
    }
    int wj = tid >> 4, wn4 = tid & 15;
    float4 wc0 = *(const float4*)&W[(2 * wj)     * 64 + wn4 * 4];
    float4 wc1 = *(const float4*)&W[(2 * wj + 1) * 64 + wn4 * 4];

    for (int kk = 0; kk < FF; kk += 32) {
        __syncthreads();
        #pragma unroll
        for (int it = 0; it < 4; it++) {
            int f = tid + 256 * it, row = f >> 3, c4 = f & 7;
            float4 v = vc[it];
            float hx = __bfloat162float(__float2bfloat16(v.x));
            float hy = __bfloat162float(__float2bfloat16(v.y));
            float hz = __bfloat162float(__float2bfloat16(v.z));
            float hw = __bfloat162float(__float2bfloat16(v.w));
            Ahi[row][c4*2+0] = packbf(hx, hy);
            Ahi[row][c4*2+1] = packbf(hz, hw);
            Alo[row][c4*2+0] = packbf(v.x - hx, v.y - hy);
            Alo[row][c4*2+1] = packbf(v.z - hz, v.w - hw);
        }
        {
            const float e0[4] = {wc0.x, wc0.y, wc0.z, wc0.w};
            const float e1[4] = {wc1.x, wc1.y, wc1.z, wc1.w};
            #pragma unroll
            for (int i = 0; i < 4; i++) {
                float h0 = __bfloat162float(__float2bfloat16(e0[i]));
                float h1 = __bfloat162float(__float2bfloat16(e1[i]));
                Bhi[wn4*4 + i][wj] = packbf(h0, h1);
                Blo[wn4*4 + i][wj] = packbf(e0[i] - h0, e1[i] - h1);
            }
        }
        __syncthreads();
        float4 vn[4], wn0, wn1;
        bool more = (kk + 32 < FF);
        if (more) {
            #pragma unroll
            for (int it = 0; it < 4; it++) {
                int f = tid + 256 * it, row = f >> 3, c4 = f & 7;
                vn[it] = make_float4(0.f, 0.f, 0.f, 0.f);
                if (m0 + row < N)
                    vn[it] = *(const float4*)&x[(long long)(m0 + row) * FF + kk + 32 + c4 * 4];
            }
            wn0 = *(const float4*)&W[(kk + 32 + 2 * wj)     * 64 + wn4 * 4];
            wn1 = *(const float4*)&W[(kk + 32 + 2 * wj + 1) * 64 + wn4 * 4];
        }
        #pragma unroll
        for (int sub = 0; sub < 2; sub++) {
            int po = sub * 8;
            uint32_t ah[4], al[4];
            ah[0] = Ahi[wrow + g    ][po + tg];
            ah[1] = Ahi[wrow + g + 8][po + tg];
            ah[2] = Ahi[wrow + g    ][po + tg + 4];
            ah[3] = Ahi[wrow + g + 8][po + tg + 4];
            al[0] = Alo[wrow + g    ][po + tg];
            al[1] = Alo[wrow + g + 8][po + tg];
            al[2] = Alo[wrow + g    ][po + tg + 4];
            al[3] = Alo[wrow + g + 8][po + tg + 4];
            #pragma unroll
            for (int t = 0; t < 8; t++) {
                uint32_t bh[2], bl[2];
                bh[0] = Bhi[t*8 + g][po + tg];
                bh[1] = Bhi[t*8 + g][po + tg + 4];
                bl[0] = Blo[t*8 + g][po + tg];
                bl[1] = Blo[t*8 + g][po + tg + 4];
                mma_bf16(c[t], ah, bh);
                mma_bf16(c[t], ah, bl);
                mma_bf16(c[t], al, bh);
            }
        }
        if (more) {
            #pragma unroll
            for (int it = 0; it < 4; it++) vc[it] = vn[it];
            wc0 = wn0; wc1 = wn1;
        }
    }

    int row0 = m0 + wrow + g;
    int row1 = row0 + 8;
    #pragma unroll
    for (int t = 0; t < 8; t++) {
        if (row0 < N)
            *(float2*)&g_h1[row0 * 64 + t*8 + tg*2] = make_float2(c[t][0], c[t][1]);
        if (row1 < N)
            *(float2*)&g_h1[row1 * 64 + t*8 + tg*2] = make_float2(c[t][2], c[t][3]);
        float as = sA[t*8 + tg*2], as2v = sA[t*8 + tg*2 + 1];
        float ad = sD[t*8 + tg*2], ad2v = sD[t*8 + tg*2 + 1];
        float s0 = c[t][0]*as + c[t][1]*as2v;
        float d0 = c[t][0]*ad + c[t][1]*ad2v;
        float s1 = c[t][2]*as + c[t][3]*as2v;
        float d1 = c[t][2]*ad + c[t][3]*ad2v;
        #pragma unroll
        for (int o = 1; o <= 2; o <<= 1) {
            s0 += __shfl_xor_sync(0xffffffffu, s0, o);
            d0 += __shfl_xor_sync(0xffffffffu, d0, o);
            s1 += __shfl_xor_sync(0xffffffffu, s1, o);
            d1 += __shfl_xor_sync(0xffffffffu, d1, o);
        }
        if (tg == 0) {
            if (row0 < N) { g_as1[row0 * 8 + t] = s0; g_ad1[row0 * 8 + t] = d0; }
            if (row1 < N) { g_as1[row1 * 8 + t] = s1; g_ad1[row1 * 8 + t] = d1; }
        }
    }
}

// -------- agg layer 1 + GEMM2 + alpha2, fused (R13 shape: proven optimum) ---
__global__ void k_agg1(const float* __restrict__ b1,
                       const float* __restrict__ W2,
                       const float* __restrict__ a_src2,
                       const float* __restrict__ a_dst2, int N) {
    __shared__ float sW2[HD * NC];    // 2.5 KB, [f*10+c]
    __shared__ float sAs2[NC], sAd2[NC], sB1[HD];
    int tid = threadIdx.x;
    for (int i = tid; i < HD * NC; i += blockDim.x) sW2[i] = W2[i];
    if (tid < NC) { sAs2[tid] = a_src2[tid]; sAd2[tid] = a_dst2[tid]; }
    if (tid < HD) sB1[tid] = b1[tid];
    __syncthreads();

    int d = (blockIdx.x * blockDim.x + tid) >> 5;
    int lane = tid & 31;
    if (d >= N) return;
    int beg = g_off[d], end = g_off[d + 1];
    float ad_l = (lane < NH) ? g_ad1[d * NH + lane] : 0.f;
    float accx = 0.f, accy = 0.f, den = 0.f;
    int s = (beg < end) ? g_csr[beg] : 0;
    for (int i = beg; i < end; i++) {
        int snext = (i + 1 < end) ? g_csr[i + 1] : 0;
        float w = 0.f;
        if (lane < NH) {
            float e = g_as1[s * NH + lane] + ad_l;
            e = e > 0.f ? e : 0.2f * e;
            w = __expf(e);
            den += w;
        }
        float wl = __shfl_sync(0xffffffffu, w, lane >> 2);
        float2 hv = *(const float2*)&g_h1[s * 64 + lane * 2];
        accx += wl * hv.x;
        accy += wl * hv.y;
        s = snext;
    }
    float denl = __shfl_sync(0xffffffffu, den, lane >> 2);
    float v0 = accx / denl + sB1[2 * lane];
    float v1 = accy / denl + sB1[2 * lane + 1];
    v0 = v0 > 0.f ? v0 : expm1f(v0);   // ELU
    v1 = v1 > 0.f ? v1 : expm1f(v1);

    // fused 64->10 projection + alpha2; record: slot0 = a_src2·h2, 1..10 = h2
    float asum = 0.f, adsum = 0.f;
    #pragma unroll
    for (int c = 0; c < NC; c++) {
        float sacc = v0 * sW2[(2 * lane) * NC + c] + v1 * sW2[(2 * lane + 1) * NC + c];
        #pragma unroll
        for (int o = 16; o; o >>= 1) sacc += __shfl_down_sync(0xffffffffu, sacc, o);
        if (lane == 0) {
            g_h2p[d * 12 + 1 + c] = sacc;
            asum  += sacc * sAs2[c];
            adsum += sacc * sAd2[c];
        }
    }
    if (lane == 0) {
        g_h2p[d * 12 + 0]  = asum;     // logit ingredient FIRST in the record
        g_h2p[d * 12 + 11] = 0.f;
        g_ad2[d] = adsum;
    }
}

// -------- aggregation layer 2 (3x LDG.128/edge; e depends on first quad) ----
__global__ void k_agg2(const float* __restrict__ b2, float* __restrict__ out, int N) {
    int d = (blockIdx.x * blockDim.x + threadIdx.x) >> 5;
    int lane = threadIdx.x & 31;
    if (d >= N) return;
    int beg = g_off[d], end = g_off[d + 1];
    float ad_d = g_ad2[d];
    float acc[NC] = {};
    float den = 0.f;
    int i = beg + lane;
    int s = (i < end) ? g_csr[i] : 0;
    for (; i < end; i += 32) {
        int snext = (i + 32 < end) ? g_csr[i + 32] : 0;
        const float4* rp = (const float4*)&g_h2p[s * 12];
        float4 f0 = rp[0], f1 = rp[1], f2 = rp[2];
        float e = f0.x + ad_d;                 // f0.x = a_src2 . h2[s] (arrives first)
        e = e > 0.f ? e : 0.2f * e;
        float w = __expf(e);
        den += w;
        acc[0] += w * f0.y; acc[1] += w * f0.z; acc[2] += w * f0.w;
        acc[3] += w * f1.x; acc[4] += w * f1.y; acc[5] += w * f1.z; acc[6] += w * f1.w;
        acc[7] += w * f2.x; acc[8] += w * f2.y; acc[9] += w * f2.z;
        s = snext;
    }
    #pragma unroll
    for (int o = 16; o; o >>= 1) {
        den += __shfl_down_sync(0xffffffffu, den, o);
        #pragma unroll
        for (int c = 0; c < NC; c++)
            acc[c] += __shfl_down_sync(0xffffffffu, acc[c], o);
    }
    if (lane == 0) {
        float inv = 1.f / den;
        float v[NC], m = -1e30f;
        #pragma unroll
        for (int c = 0; c < NC; c++) {
            v[c] = acc[c] * inv + b2[c];
            m = fmaxf(m, v[c]);
        }
        float ssum = 0.f;
        #pragma unroll
        for (int c = 0; c < NC; c++) ssum += __expf(v[c] - m);
        float l = __logf(ssum);
        #pragma unroll
        for (int c = 0; c < NC; c++) out[d * NC + c] = v[c] - m - l;
    }
}

// ---------------------------------------------------------------------------
extern "C" void kernel_launch(void* const* d_in, const int* in_sizes, int n_in,
                              void* d_out, int out_size) {
    const float* x   = (const float*)d_in[0];
    const void*  ei  = d_in[1];
    const float* W1  = (const float*)d_in[2];
    const float* as1 = (const float*)d_in[3];
    const float* ad1 = (const float*)d_in[4];
    const float* b1  = (const float*)d_in[5];
    const float* W2  = (const float*)d_in[6];
    const float* as2 = (const float*)d_in[7];
    const float* ad2 = (const float*)d_in[8];
    const float* b2  = (const float*)d_in[9];

    int       N  = in_sizes[0] / FF;
    long long E  = (long long)in_sizes[1] / 2;
    long long EN = E + (long long)N;
    int nb = (N + SCANB - 1) / SCANB;
    float* out = (float*)d_out;

    cudaStream_t s1 = 0;
    cudaEvent_t ev0 = 0, ev1 = 0;
    bool forked =
        cudaStreamCreateWithFlags(&s1, cudaStreamNonBlocking) == cudaSuccess &&
        cudaEventCreateWithFlags(&ev0, cudaEventDisableTiming) == cudaSuccess &&
        cudaEventCreateWithFlags(&ev1, cudaEventDisableTiming) == cudaSuccess;

    if (forked) forked = cudaEventRecord(ev0, 0) == cudaSuccess &&
                         cudaStreamWaitEvent(s1, ev0, 0) == cudaSuccess;

    cudaStream_t cs = forked ? s1 : 0;

    // ---- branch A: CSR build (edge_index only) ----
    k_zero<<<(N + 255) / 256, 256, 0, cs>>>((const long long*)ei, E, N);
    k_hist<<<(unsigned)((EN + 255) / 256), 256, 0, cs>>>(ei, E, N);
    k_scan1<<<nb, SCANB, 0, cs>>>(N);
    k_scan3<<<nb, SCANB, 0, cs>>>(N, (int)EN, nb);
    k_scatter<<<(unsigned)((EN + 255) / 256), 256, 0, cs>>>(ei, E, N);
    if (forked) forked = cudaEventRecord(ev1, s1) == cudaSuccess;

    // ---- branch B: projection GEMM (x, W1 only) ----
    k_gemm1<<<(N + 127) / 128, 256>>>(x, W1, as1, ad1, N);

    // ---- join + tail ----
    if (forked) cudaStreamWaitEvent(0, ev1, 0);

    k_agg1<<<(unsigned)(((long long)N * 32 + 255) / 256), 256>>>(b1, W2, as2, ad2, N);
    k_agg2<<<(unsigned)(((long long)N * 32 + 255) / 256), 256>>>(b2, out, N);
    // Streams/events intentionally not destroyed (illegal mid-capture;
    // host-side handles only, O(1) calls, no device memory involved).
}

// round 17
// speedup vs baseline: 1.4884x; 1.0365x over previous
#include <cuda_runtime.h>
#include <cuda_bf16.h>
#include <cstdint>

#define FF  512
#define HD  64
#define NH  8
#define NC  10
#define NMAX 50000
#define EMAX 1700000
#define SCANB 256
#define NBMAX ((NMAX + SCANB - 1) / SCANB)

// -------- scratch (static device globals; zero-initialized at load) --------
static __device__ float g_h1  [NMAX*HD];
static __device__ float g_as1 [NMAX*NH];
static __device__ float g_ad1 [NMAX*NH];
static __device__ float g_h2p [NMAX*12];   // h2[0..9], slot10 = a_src2·h2
static __device__ float g_ad2 [NMAX];
static __device__ int   g_cnt [NMAX];      // re-zeroed by k_scan1 every run
static __device__ int   g_off [NMAX+1];
static __device__ int   g_cur [NMAX];
static __device__ int   g_csr [EMAX];
static __device__ int   g_bsum[NBMAX];
static __device__ int   g_is32;

__device__ __forceinline__ uint32_t packbf(float lo16, float hi16) {
    uint32_t r;
    asm("cvt.rn.bf16x2.f32 %0, %1, %2;" : "=r"(r) : "f"(hi16), "f"(lo16));
    return r;
}
__device__ __forceinline__ void mma_bf16(float* c, const uint32_t* a, const uint32_t* b) {
    asm volatile(
        "mma.sync.aligned.m16n8k16.row.col.f32.bf16.bf16.f32 "
        "{%0,%1,%2,%3}, {%4,%5,%6,%7}, {%8,%9}, {%0,%1,%2,%3};"
        : "+f"(c[0]), "+f"(c[1]), "+f"(c[2]), "+f"(c[3])
        : "r"(a[0]), "r"(a[1]), "r"(a[2]), "r"(a[3]), "r"(b[0]), "r"(b[1]));
}

// -------- edge dtype sniffer (1 warp) ---------------------------------------
__global__ void k_detect(const long long* __restrict__ e, long long E, long long N) {
    if (threadIdx.x == 0) {
        int is32 = 0;
        long long cnt = E < 256 ? E : 256;
        for (long long j = 0; j < cnt; j++) {
            long long v = e[j];
            if (v < 0 || v >= N) { is32 = 1; break; }
        }
        g_is32 = is32;
    }
}

// -------- CSR histogram -----------------------------------------------------
__global__ void k_hist(const void* __restrict__ ei, long long E, int N) {
    long long i = (long long)blockIdx.x * blockDim.x + threadIdx.x;
    long long EN = E + (long long)N;
    if (i >= EN) return;
    int d;
    if (i >= E) d = (int)(i - E);
    else if (g_is32) d = ((const int*)ei)[E + i];
    else             d = (int)((const long long*)ei)[E + i];
    atomicAdd(&g_cnt[d], 1);
}

// -------- scan level 1 (also re-zeros g_cnt for the next graph replay) ------
__global__ void k_scan1(int N) {
    __shared__ int sh[SCANB];
    int t = threadIdx.x;
    int i = blockIdx.x * SCANB + t;
    int v = (i < N) ? g_cnt[i] : 0;
    if (i < N) g_cnt[i] = 0;          // fold k_zero into the scan pass
    sh[t] = v;
    __syncthreads();
    #pragma unroll
    for (int o = 1; o < SCANB; o <<= 1) {
        int u = (t >= o) ? sh[t - o] : 0;
        __syncthreads();
        sh[t] += u;
        __syncthreads();
    }
    if (i < N) g_off[i] = sh[t] - v;
    if (t == SCANB - 1) g_bsum[blockIdx.x] = sh[t];
}

// -------- scan level 2+3 merged ---------------------------------------------
__global__ void k_scan3(int N, int total, int nb) {
    __shared__ int sh[SCANB];
    int t = threadIdx.x;
    int v = (t < nb && t < blockIdx.x) ? g_bsum[t] : 0;
    sh[t] = v;
    __syncthreads();
    #pragma unroll
    for (int o = SCANB / 2; o; o >>= 1) {
        if (t < o) sh[t] += sh[t + o];
        __syncthreads();
    }
    int base = sh[0];
    int i = blockIdx.x * SCANB + t;
    if (i < N) {
        int o = g_off[i] + base;
        g_off[i] = o;
        g_cur[i] = o;
    }
    if (i == 0) g_off[N] = total;
}

// -------- CSR scatter -------------------------------------------------------
__global__ void k_scatter(const void* __restrict__ ei, long long E, int N) {
    long long i = (long long)blockIdx.x * blockDim.x + threadIdx.x;
    long long EN = E + (long long)N;
    if (i >= EN) return;
    int s, d;
    if (i >= E) { s = d = (int)(i - E); }
    else if (g_is32) { const int* p = (const int*)ei; s = p[i]; d = p[E + i]; }
    else { const long long* p = (const long long*)ei; s = (int)p[i]; d = (int)p[E + i]; }
    int pos = atomicAdd(&g_cur[d], 1);
    g_csr[pos] = s;
}

// -------- GEMM1 (tensor cores): split-bf16, double-buffered, alpha1 fused ---
__global__ void k_gemm1(const float* __restrict__ x, const float* __restrict__ W,
                        const float* __restrict__ a_src, const float* __restrict__ a_dst,
                        int N) {
    __shared__ uint32_t Ahi[128][20], Alo[128][20];
    __shared__ uint32_t Bhi[64][20],  Blo[64][20];
    __shared__ float sA[64], sD[64];

    int tid  = threadIdx.x;
    int lane = tid & 31;
    int warp = tid >> 5;
    int m0   = blockIdx.x * 128;
    int wrow = warp * 16;
    int g = lane >> 2, tg = lane & 3;

    if (tid < 64) { sA[tid] = a_src[tid]; sD[tid] = a_dst[tid]; }

    float c[8][4] = {};

    float4 vc[4];
    #pragma unroll
    for (int it = 0; it < 4; it++) {
        int f = tid + 256 * it, row = f >> 3, c4 = f & 7;
        vc[it] = make_float4(0.f, 0.f, 0.f, 0.f);
        if (m0 + row < N)
            vc[it] = *(const float4*)&x[(long long)(m0 + row) * FF + c4 * 4];
    }
    int wj = tid >> 4, wn4 = tid & 15;
    float4 wc0 = *(const float4*)&W[(2 * wj)     * 64 + wn4 * 4];
    float4 wc1 = *(const float4*)&W[(2 * wj + 1) * 64 + wn4 * 4];

    for (int kk = 0; kk < FF; kk += 32) {
        __syncthreads();
        #pragma unroll
        for (int it = 0; it < 4; it++) {
            int f = tid + 256 * it, row = f >> 3, c4 = f & 7;
            float4 v = vc[it];
            float hx = __bfloat162float(__float2bfloat16(v.x));
            float hy = __bfloat162float(__float2bfloat16(v.y));
            float hz = __bfloat162float(__float2bfloat16(v.z));
            float hw = __bfloat162float(__float2bfloat16(v.w));
            Ahi[row][c4*2+0] = packbf(hx, hy);
            Ahi[row][c4*2+1] = packbf(hz, hw);
            Alo[row][c4*2+0] = packbf(v.x - hx, v.y - hy);
            Alo[row][c4*2+1] = packbf(v.z - hz, v.w - hw);
        }
        {
            const float e0[4] = {wc0.x, wc0.y, wc0.z, wc0.w};
            const float e1[4] = {wc1.x, wc1.y, wc1.z, wc1.w};
            #pragma unroll
            for (int i = 0; i < 4; i++) {
                float h0 = __bfloat162float(__float2bfloat16(e0[i]));
                float h1 = __bfloat162float(__float2bfloat16(e1[i]));
                Bhi[wn4*4 + i][wj] = packbf(h0, h1);
                Blo[wn4*4 + i][wj] = packbf(e0[i] - h0, e1[i] - h1);
            }
        }
        __syncthreads();
        float4 vn[4], wn0, wn1;
        bool more = (kk + 32 < FF);
        if (more) {
            #pragma unroll
            for (int it = 0; it < 4; it++) {
                int f = tid + 256 * it, row = f >> 3, c4 = f & 7;
                vn[it] = make_float4(0.f, 0.f, 0.f, 0.f);
                if (m0 + row < N)
                    vn[it] = *(const float4*)&x[(long long)(m0 + row) * FF + kk + 32 + c4 * 4];
            }
            wn0 = *(const float4*)&W[(kk + 32 + 2 * wj)     * 64 + wn4 * 4];
            wn1 = *(const float4*)&W[(kk + 32 + 2 * wj + 1) * 64 + wn4 * 4];
        }
        #pragma unroll
        for (int sub = 0; sub < 2; sub++) {
            int po = sub * 8;
            uint32_t ah[4], al[4];
            ah[0] = Ahi[wrow + g    ][po + tg];
            ah[1] = Ahi[wrow + g + 8][po + tg];
            ah[2] = Ahi[wrow + g    ][po + tg + 4];
            ah[3] = Ahi[wrow + g + 8][po + tg + 4];
            al[0] = Alo[wrow + g    ][po + tg];
            al[1] = Alo[wrow + g + 8][po + tg];
            al[2] = Alo[wrow + g    ][po + tg + 4];
            al[3] = Alo[wrow + g + 8][po + tg + 4];
            #pragma unroll
            for (int t = 0; t < 8; t++) {
                uint32_t bh[2], bl[2];
                bh[0] = Bhi[t*8 + g][po + tg];
                bh[1] = Bhi[t*8 + g][po + tg + 4];
                bl[0] = Blo[t*8 + g][po + tg];
                bl[1] = Blo[t*8 + g][po + tg + 4];
                mma_bf16(c[t], ah, bh);
                mma_bf16(c[t], ah, bl);
                mma_bf16(c[t], al, bh);
            }
        }
        if (more) {
            #pragma unroll
            for (int it = 0; it < 4; it++) vc[it] = vn[it];
            wc0 = wn0; wc1 = wn1;
        }
    }

    int row0 = m0 + wrow + g;
    int row1 = row0 + 8;
    #pragma unroll
    for (int t = 0; t < 8; t++) {
        if (row0 < N)
            *(float2*)&g_h1[row0 * 64 + t*8 + tg*2] = make_float2(c[t][0], c[t][1]);
        if (row1 < N)
            *(float2*)&g_h1[row1 * 64 + t*8 + tg*2] = make_float2(c[t][2], c[t][3]);
        float as = sA[t*8 + tg*2], as2v = sA[t*8 + tg*2 + 1];
        float ad = sD[t*8 + tg*2], ad2v = sD[t*8 + tg*2 + 1];
        float s0 = c[t][0]*as + c[t][1]*as2v;
        float d0 = c[t][0]*ad + c[t][1]*ad2v;
        float s1 = c[t][2]*as + c[t][3]*as2v;
        float d1 = c[t][2]*ad + c[t][3]*ad2v;
        #pragma unroll
        for (int o = 1; o <= 2; o <<= 1) {
            s0 += __shfl_xor_sync(0xffffffffu, s0, o);
            d0 += __shfl_xor_sync(0xffffffffu, d0, o);
            s1 += __shfl_xor_sync(0xffffffffu, s1, o);
            d1 += __shfl_xor_sync(0xffffffffu, d1, o);
        }
        if (tg == 0) {
            if (row0 < N) { g_as1[row0 * 8 + t] = s0; g_ad1[row0 * 8 + t] = d0; }
            if (row1 < N) { g_as1[row1 * 8 + t] = s1; g_ad1[row1 * 8 + t] = d1; }
        }
    }
}

// -------- agg layer 1 + GEMM2 + alpha2, fused (R13 shape: proven optimum) ---
__global__ void k_agg1(const float* __restrict__ b1,
                       const float* __restrict__ W2,
                       const float* __restrict__ a_src2,
                       const float* __restrict__ a_dst2, int N) {
    __shared__ float sW2[HD * NC];    // 2.5 KB, [f*10+c]
    __shared__ float sAs2[NC], sAd2[NC], sB1[HD];
    int tid = threadIdx.x;
    for (int i = tid; i < HD * NC; i += blockDim.x) sW2[i] = W2[i];
    if (tid < NC) { sAs2[tid] = a_src2[tid]; sAd2[tid] = a_dst2[tid]; }
    if (tid < HD) sB1[tid] = b1[tid];
    __syncthreads();

    int d = (blockIdx.x * blockDim.x + tid) >> 5;
    int lane = tid & 31;
    if (d >= N) return;
    int beg = g_off[d], end = g_off[d + 1];
    float ad_l = (lane < NH) ? g_ad1[d * NH + lane] : 0.f;
    float accx = 0.f, accy = 0.f, den = 0.f;
    int s = (beg < end) ? g_csr[beg] : 0;
    for (int i = beg; i < end; i++) {
        int snext = (i + 1 < end) ? g_csr[i + 1] : 0;
        float w = 0.f;
        if (lane < NH) {
            float e = g_as1[s * NH + lane] + ad_l;
            e = e > 0.f ? e : 0.2f * e;
            w = __expf(e);
            den += w;
        }
        float wl = __shfl_sync(0xffffffffu, w, lane >> 2);
        float2 hv = *(const float2*)&g_h1[s * 64 + lane * 2];
        accx += wl * hv.x;
        accy += wl * hv.y;
        s = snext;
    }
    float denl = __shfl_sync(0xffffffffu, den, lane >> 2);
    float v0 = accx / denl + sB1[2 * lane];
    float v1 = accy / denl + sB1[2 * lane + 1];
    v0 = v0 > 0.f ? v0 : expm1f(v0);   // ELU
    v1 = v1 > 0.f ? v1 : expm1f(v1);

    // fused 64->10 projection + alpha2 (record: h2 in 0..9, logit in slot 10)
    float asum = 0.f, adsum = 0.f;
    #pragma unroll
    for (int c = 0; c < NC; c++) {
        float sacc = v0 * sW2[(2 * lane) * NC + c] + v1 * sW2[(2 * lane + 1) * NC + c];
        #pragma unroll
        for (int o = 16; o; o >>= 1) sacc += __shfl_down_sync(0xffffffffu, sacc, o);
        if (lane == 0) {
            g_h2p[d * 12 + c] = sacc;
            asum  += sacc * sAs2[c];
            adsum += sacc * sAd2[c];
        }
    }
    if (lane == 0) {
        g_h2p[d * 12 + 10] = asum;
        g_h2p[d * 12 + 11] = 0.f;
        g_ad2[d] = adsum;
    }
}

// -------- aggregation layer 2: HALF-WARP per dst (two dsts per warp) --------
// Lanes 0..15 handle dst 2w, lanes 16..31 handle dst 2w+1. Per-lane register
// state identical to the single-dst version; warp count halves and the
// per-dst serial epilogue runs 2-wide in each warp.
__global__ void k_agg2(const float* __restrict__ b2, float* __restrict__ out, int N) {
    int w = (blockIdx.x * blockDim.x + threadIdx.x) >> 5;
    int lane = threadIdx.x & 31;
    int half = lane >> 4, hl = lane & 15;
    int d = w * 2 + half;
    bool valid = (d < N);
    int beg = valid ? g_off[d] : 0, end = valid ? g_off[d + 1] : 0;
    float ad_d = valid ? g_ad2[d] : 0.f;
    float acc[NC] = {};
    float den = 0.f;
    int i = beg + hl;
    int s = (i < end) ? g_csr[i] : 0;
    for (; i < end; i += 16) {
        int snext = (i + 16 < end) ? g_csr[i + 16] : 0;
        const float4* rp = (const float4*)&g_h2p[s * 12];
        float4 f0 = rp[0], f1 = rp[1], f2 = rp[2];
        float e = f2.z + ad_d;                 // f2.z = a_src2 . h2[s]
        e = e > 0.f ? e : 0.2f * e;
        float wgt = __expf(e);
        den += wgt;
        acc[0] += wgt * f0.x; acc[1] += wgt * f0.y; acc[2] += wgt * f0.z; acc[3] += wgt * f0.w;
        acc[4] += wgt * f1.x; acc[5] += wgt * f1.y; acc[6] += wgt * f1.z; acc[7] += wgt * f1.w;
        acc[8] += wgt * f2.x; acc[9] += wgt * f2.y;
        s = snext;
    }
    // reduce within each 16-lane half (offsets stay inside the half)
    #pragma unroll
    for (int o = 8; o; o >>= 1) {
        den += __shfl_down_sync(0xffffffffu, den, o);
        #pragma unroll
        for (int c = 0; c < NC; c++)
            acc[c] += __shfl_down_sync(0xffffffffu, acc[c], o);
    }
    if (hl == 0 && valid) {
        float inv = 1.f / den;
        float v[NC], m = -1e30f;
        #pragma unroll
        for (int c = 0; c < NC; c++) {
            v[c] = acc[c] * inv + b2[c];
            m = fmaxf(m, v[c]);
        }
        float ssum = 0.f;
        #pragma unroll
        for (int c = 0; c < NC; c++) ssum += __expf(v[c] - m);
        float l = __logf(ssum);
        #pragma unroll
        for (int c = 0; c < NC; c++) out[d * NC + c] = v[c] - m - l;
    }
}

// ---------------------------------------------------------------------------
extern "C" void kernel_launch(void* const* d_in, const int* in_sizes, int n_in,
                              void* d_out, int out_size) {
    const float* x   = (const float*)d_in[0];
    const void*  ei  = d_in[1];
    const float* W1  = (const float*)d_in[2];
    const float* as1 = (const float*)d_in[3];
    const float* ad1 = (const float*)d_in[4];
    const float* b1  = (const float*)d_in[5];
    const float* W2  = (const float*)d_in[6];
    const float* as2 = (const float*)d_in[7];
    const float* ad2 = (const float*)d_in[8];
    const float* b2  = (const float*)d_in[9];

    int       N  = in_sizes[0] / FF;
    long long E  = (long long)in_sizes[1] / 2;
    long long EN = E + (long long)N;
    int nb = (N + SCANB - 1) / SCANB;
    int npairs = (N + 1) / 2;
    float* out = (float*)d_out;

    cudaStream_t s1 = 0;
    cudaEvent_t ev0 = 0, ev1 = 0;
    bool forked =
        cudaStreamCreateWithFlags(&s1, cudaStreamNonBlocking) == cudaSuccess &&
        cudaEventCreateWithFlags(&ev0, cudaEventDisableTiming) == cudaSuccess &&
        cudaEventCreateWithFlags(&ev1, cudaEventDisableTiming) == cudaSuccess;

    if (forked) forked = cudaEventRecord(ev0, 0) == cudaSuccess &&
                         cudaStreamWaitEvent(s1, ev0, 0) == cudaSuccess;

    cudaStream_t cs = forked ? s1 : 0;

    // ---- branch A: CSR build (edge_index only) ----
    k_detect<<<1, 32, 0, cs>>>((const long long*)ei, E, N);
    k_hist<<<(unsigned)((EN + 255) / 256), 256, 0, cs>>>(ei, E, N);
    k_scan1<<<nb, SCANB, 0, cs>>>(N);
    k_scan3<<<nb, SCANB, 0, cs>>>(N, (int)EN, nb);
    k_scatter<<<(unsigned)((EN + 255) / 256), 256, 0, cs>>>(ei, E, N);
    if (forked) forked = cudaEventRecord(ev1, s1) == cudaSuccess;

    // ---- branch B: projection GEMM (x, W1 only) ----
    k_gemm1<<<(N + 127) / 128, 256>>>(x, W1, as1, ad1, N);

    // ---- join + tail ----
    if (forked) cudaStreamWaitEvent(0, ev1, 0);

    k_agg1<<<(unsigned)(((long long)N * 32 + 255) / 256), 256>>>(b1, W2, as2, ad2, N);
    k_agg2<<<(unsigned)(((long long)npairs * 32 + 255) / 256), 256>>>(b2, out, N);
    // Streams/events intentionally not destroyed (illegal mid-capture;
    // host-side handles only, O(1) calls, no device memory involved).
}